// round 16
// baseline (speedup 1.0000x reference)
#include <cuda_runtime.h>

// Problem-fixed sizes (from reference setup_inputs).
#define MAX_N_VARS    1000000
#define MAX_N_CONSTRS 1000000
#define FULLMASK 0xffffffffu

// Scratch (allocs forbidden -> __device__ globals).
__device__ float g_values[MAX_N_VARS];
__device__ float g_ax[MAX_N_CONSTRS];

// ---------------------------------------------------------------------------
// Kernel 1: values = pred*(ub-lb)+lb ; zero ax ; zero out scalar.
// Triggers PDL immediately so the SpMV grid can launch while this runs.
// ---------------------------------------------------------------------------
__global__ void prep_kernel(const float4* __restrict__ pred,
                            const float4* __restrict__ lb,
                            const float4* __restrict__ ub,
                            int n_vars4, int n_constrs4,
                            float* __restrict__ out) {
    cudaTriggerProgrammaticLaunchCompletion();
    int i = blockIdx.x * blockDim.x + threadIdx.x;
    if (i < n_vars4) {
        float4 p = __ldcg(pred + i);
        float4 l = __ldcg(lb + i);
        float4 u = __ldcg(ub + i);
        float4 v;
        v.x = fmaf(p.x, u.x - l.x, l.x);
        v.y = fmaf(p.y, u.y - l.y, l.y);
        v.z = fmaf(p.z, u.z - l.z, l.z);
        v.w = fmaf(p.w, u.w - l.w, l.w);
        reinterpret_cast<float4*>(g_values)[i] = v;
    }
    if (i < n_constrs4) {
        reinterpret_cast<float4*>(g_ax)[i] = make_float4(0.f, 0.f, 0.f, 0.f);
    }
    if (i == 0) out[0] = 0.0f;
}

// ---------------------------------------------------------------------------
// Kernel 2: segmented scatter-add. ITEMS=4 (at the L1tex wavefront floor).
// PDL: trigger at entry; stream loads (independent of prep) issue before
// cudaGridDependencySynchronize(); gathers + atomics after.
// Tail-merge extended to 3 hops: runs span ~4-5 threads at ITEMS=4, so a
// closing thread can absorb tails across up to two passthrough lanes plus
// its immediate predecessor (~0.7M fewer atomics vs 2-hop).
// ---------------------------------------------------------------------------
#define ITEMS 4
#define SPMV_THREADS 512

__global__ void __launch_bounds__(SPMV_THREADS)
spmv_kernel(const float* __restrict__ coeff,
            const int*   __restrict__ cidx,
            const int*   __restrict__ vidx,
            int nnz) {
    cudaTriggerProgrammaticLaunchCompletion();

    int base = (blockIdx.x * blockDim.x + threadIdx.x) * ITEMS;
    unsigned lane = threadIdx.x & 31u;
    bool active = base < nnz;
    bool full = active && (base + ITEMS <= nnz);

    // ---- phase 1: stream loads (do NOT depend on prep) ----
    float c[ITEMS];
    int   ci[ITEMS];
    int4  b = make_int4(0, 0, 0, 0);
    int   count = 0;
    if (full) {
        count = ITEMS;
        float4 f = *reinterpret_cast<const float4*>(coeff + base);
        int4   a = *reinterpret_cast<const int4*>(cidx + base);
        b = *reinterpret_cast<const int4*>(vidx + base);
        c[0] = f.x; c[1] = f.y; c[2] = f.z; c[3] = f.w;
        ci[0] = a.x; ci[1] = a.y; ci[2] = a.z; ci[3] = a.w;
    } else if (active) {
        count = nnz - base;
        for (int j = 0; j < count; j++) {
            c[j]  = coeff[base + j];
            ci[j] = cidx[base + j];
        }
    }

    // ---- wait for prep (g_values complete, g_ax zeroed) ----
    cudaGridDependencySynchronize();

    int   head_key = -1;   // sentinel: never matches a real key
    int   tail_key = -2;   // distinct sentinel (also breaks passthrough test)
    float head_acc = 0.f;
    float tail_acc = 0.f;
    bool  has_b    = false;  // head run closed inside this tile

    if (active) {
        if (full) {
            c[0] *= __ldcg(g_values + b.x);
            c[1] *= __ldcg(g_values + b.y);
            c[2] *= __ldcg(g_values + b.z);
            c[3] *= __ldcg(g_values + b.w);
        } else {
            for (int j = 0; j < count; j++)
                c[j] *= __ldcg(g_values + vidx[base + j]);
        }

        head_key = ci[0];
        int   cur = ci[0];
        float acc = c[0];
#pragma unroll
        for (int j = 1; j < ITEMS; j++) {
            if (j < count) {
                if (ci[j] == cur) {
                    acc += c[j];
                } else {
                    if (!has_b) { head_acc = acc; has_b = true; }
                    else        atomicAdd(&g_ax[cur], acc);  // interior run
                    cur = ci[j];
                    acc = c[j];
                }
            }
        }
        tail_key = cur;
        tail_acc = acc;
    }

    // ---- cross-thread merge, up to 3 hops (all lanes shuffle) ----
    // passthrough: whole tile is a single run (head==tail, nothing closed).
    bool pass = (head_key == tail_key) && !has_b;

    int   prev_tail_key  = __shfl_up_sync(FULLMASK, tail_key, 1);
    float prev_tail_acc  = __shfl_up_sync(FULLMASK, tail_acc, 1);
    int   prev_pass      = __shfl_up_sync(FULLMASK, (int)pass, 1);
    int   prev2_tail_key = __shfl_up_sync(FULLMASK, tail_key, 2);
    float prev2_tail_acc = __shfl_up_sync(FULLMASK, tail_acc, 2);
    int   prev2_pass     = __shfl_up_sync(FULLMASK, (int)pass, 2);
    int   prev3_tail_key = __shfl_up_sync(FULLMASK, tail_key, 3);
    float prev3_tail_acc = __shfl_up_sync(FULLMASK, tail_acc, 3);

    int   next_head_key  = __shfl_down_sync(FULLMASK, head_key, 1);
    int   next_has_b     = __shfl_down_sync(FULLMASK, (int)has_b, 1);
    int   next_pass      = __shfl_down_sync(FULLMASK, (int)pass, 1);
    int   next2_head_key = __shfl_down_sync(FULLMASK, head_key, 2);
    int   next2_has_b    = __shfl_down_sync(FULLMASK, (int)has_b, 2);
    int   next2_pass     = __shfl_down_sync(FULLMASK, (int)pass, 2);
    int   next3_head_key = __shfl_down_sync(FULLMASK, head_key, 3);
    int   next3_has_b    = __shfl_down_sync(FULLMASK, (int)has_b, 3);

    // k-hop absorb: all intervening lanes are passthrough, keys match,
    // and I close the run inside my tile (has_b).
    bool take_prev  = (lane > 0) && has_b && (prev_tail_key == head_key);
    bool take_prev2 = (lane > 1) && has_b && prev_pass &&
                      (prev2_tail_key == head_key);
    bool take_prev3 = (lane > 2) && has_b && prev_pass && prev2_pass &&
                      (prev3_tail_key == head_key);
    // Mirror conditions: my tail is absorbed by the matching absorber.
    bool absorbed1 = (lane < 31) && next_has_b && (next_head_key == tail_key);
    bool absorbed2 = (lane < 30) && next_pass && next2_has_b &&
                     (next2_head_key == tail_key);
    bool absorbed3 = (lane < 29) && next_pass && next2_pass && next3_has_b &&
                     (next3_head_key == tail_key);

    if (take_prev)  head_acc += prev_tail_acc;
    if (take_prev2) head_acc += prev2_tail_acc;
    if (take_prev3) head_acc += prev3_tail_acc;

    if (active && has_b)
        atomicAdd(&g_ax[head_key], head_acc);
    if (active && !(absorbed1 || absorbed2 || absorbed3))
        atomicAdd(&g_ax[tail_key], tail_acc);
}

// ---------------------------------------------------------------------------
// Kernel 3: violations + mean reduction. PDL: rhs/sense loads (independent of
// spmv) issue before the dependency sync; g_ax read after.
// sense: 1 -> relu(ax-b), 2 -> relu(b-ax), 3 -> |ax-b|, else 0.
// ---------------------------------------------------------------------------
#define LOSS_THREADS 512

__global__ void __launch_bounds__(LOSS_THREADS)
loss_kernel(const float4* __restrict__ rhs,
            const int4*   __restrict__ sense,
            int n_constrs4, float inv_n,
            float* __restrict__ out) {
    __shared__ float sdata[LOSS_THREADS / 32];
    int i = blockIdx.x * blockDim.x + threadIdx.x;
    bool active = i < n_constrs4;

    float4 r = make_float4(0.f, 0.f, 0.f, 0.f);
    int4   s = make_int4(0, 0, 0, 0);
    if (active) {
        r = __ldcg(rhs + i);
        s = __ldcg(sense + i);
    }

    cudaGridDependencySynchronize();  // wait for spmv (g_ax complete)

    float local = 0.0f;
    if (active) {
        float4 a = __ldcg(reinterpret_cast<const float4*>(g_ax) + i);
        float d0 = a.x - r.x, d1 = a.y - r.y, d2 = a.z - r.z, d3 = a.w - r.w;
        float v;
        v = (s.x == 1) ? fmaxf(d0, 0.f) : (s.x == 2) ? fmaxf(-d0, 0.f) : (s.x == 3) ? fabsf(d0) : 0.f;
        local += v;
        v = (s.y == 1) ? fmaxf(d1, 0.f) : (s.y == 2) ? fmaxf(-d1, 0.f) : (s.y == 3) ? fabsf(d1) : 0.f;
        local += v;
        v = (s.z == 1) ? fmaxf(d2, 0.f) : (s.z == 2) ? fmaxf(-d2, 0.f) : (s.z == 3) ? fabsf(d2) : 0.f;
        local += v;
        v = (s.w == 1) ? fmaxf(d3, 0.f) : (s.w == 2) ? fmaxf(-d3, 0.f) : (s.w == 3) ? fabsf(d3) : 0.f;
        local += v;
    }
#pragma unroll
    for (int off = 16; off > 0; off >>= 1)
        local += __shfl_down_sync(FULLMASK, local, off);
    int lane = threadIdx.x & 31;
    int wid  = threadIdx.x >> 5;
    if (lane == 0) sdata[wid] = local;
    __syncthreads();
    int nwarps = LOSS_THREADS / 32;
    if (wid == 0) {
        float v = (lane < nwarps) ? sdata[lane] : 0.0f;
#pragma unroll
        for (int off = 16; off > 0; off >>= 1)
            v += __shfl_down_sync(FULLMASK, v, off);
        if (lane == 0) atomicAdd(out, v * inv_n);
    }
}

// Tail-handling loss kernel (safety; never launched for the fixed 1M size).
__global__ void loss_tail_kernel(const float* __restrict__ rhs,
                                 const int*   __restrict__ sense,
                                 int start, int n_constrs, float inv_n,
                                 float* __restrict__ out) {
    int i = start + blockIdx.x * blockDim.x + threadIdx.x;
    if (i < n_constrs) {
        float diff = g_ax[i] - rhs[i];
        int sv = sense[i];
        float v = (sv == 1) ? fmaxf(diff, 0.f)
                : (sv == 2) ? fmaxf(-diff, 0.f)
                : (sv == 3) ? fabsf(diff) : 0.f;
        atomicAdd(out, v * inv_n);
    }
}

// ---------------------------------------------------------------------------
// Launch. Input order: pred, coeff, constr_rhs, var_lb, var_ub,
// constr_idx, var_idx, constr_sense, n_vars, n_constrs.
// prep -> spmv -> loss chained with Programmatic Dependent Launch.
// ---------------------------------------------------------------------------
extern "C" void kernel_launch(void* const* d_in, const int* in_sizes, int n_in,
                              void* d_out, int out_size) {
    const float* pred  = (const float*)d_in[0];
    const float* coeff = (const float*)d_in[1];
    const float* rhs   = (const float*)d_in[2];
    const float* lb    = (const float*)d_in[3];
    const float* ub    = (const float*)d_in[4];
    const int*   cidx  = (const int*)d_in[5];
    const int*   vidx  = (const int*)d_in[6];
    const int*   sense = (const int*)d_in[7];

    int n_vars    = in_sizes[0];
    int nnz       = in_sizes[1];
    int n_constrs = in_sizes[2];

    float* out = (float*)d_out;

    int n_vars4    = n_vars / 4;
    int n_constrs4 = n_constrs / 4;
    int n_max4 = n_vars4 > n_constrs4 ? n_vars4 : n_constrs4;

    // prep: plain launch (first in chain).
    prep_kernel<<<(n_max4 + 255) / 256, 256>>>(
        (const float4*)pred, (const float4*)lb, (const float4*)ub,
        n_vars4, n_constrs4, out);

    cudaLaunchAttribute pdl_attr[1];
    pdl_attr[0].id = cudaLaunchAttributeProgrammaticStreamSerialization;
    pdl_attr[0].val.programmaticStreamSerializationAllowed = 1;

    // spmv: PDL launch (overlaps its stream loads with prep).
    {
        long long n_threads_spmv = ((long long)nnz + ITEMS - 1) / ITEMS;
        int blocks_spmv = (int)((n_threads_spmv + SPMV_THREADS - 1) / SPMV_THREADS);
        cudaLaunchConfig_t cfg = {};
        cfg.gridDim = dim3(blocks_spmv, 1, 1);
        cfg.blockDim = dim3(SPMV_THREADS, 1, 1);
        cfg.attrs = pdl_attr;
        cfg.numAttrs = 1;
        cudaLaunchKernelEx(&cfg, spmv_kernel, coeff, cidx, vidx, nnz);
    }

    // loss: PDL launch (overlaps rhs/sense loads with spmv).
    float inv_n = 1.0f / (float)n_constrs;
    {
        int blocks_loss = (n_constrs4 + LOSS_THREADS - 1) / LOSS_THREADS;
        cudaLaunchConfig_t cfg = {};
        cfg.gridDim = dim3(blocks_loss, 1, 1);
        cfg.blockDim = dim3(LOSS_THREADS, 1, 1);
        cfg.attrs = pdl_attr;
        cfg.numAttrs = 1;
        cudaLaunchKernelEx(&cfg, loss_kernel,
                           (const float4*)rhs, (const int4*)sense,
                           n_constrs4, inv_n, out);
    }

    int tail_start = n_constrs4 * 4;
    if (tail_start < n_constrs) {
        int tail = n_constrs - tail_start;
        loss_tail_kernel<<<(tail + 255) / 256, 256>>>(
            rhs, sense, tail_start, n_constrs, inv_n, out);
    }
}